// round 16
// baseline (speedup 1.0000x reference)
#include <cuda_runtime.h>
#include <cuda_fp16.h>
#include <cstdint>
#include <math.h>

// Problem constants
#define BB 8
#define PP 512
#define LL 64
#define HH 128
#define NPT 20
#define NLT 16
#define GRIDX 148
#define LIST_CAP 32768         // P*L pairs per complex (worst case)

// SMEM layout. Half regions first (indices in halves), float tail after.
#define W1R_PITCH_H 40
#define W_PITCH_H   136
#define H_PITCH_H   136
#define H_W1R 0                // 128*40  = 5120 halves
#define H_W2  5120             // 128*136 = 17408
#define H_W3  22528
#define H_H   39936            // 4 pipeline buffers [64][136] halves (8704 each)
#define F_MSK   37376          // [4][64] floats
#define F_B2    37632          // [128]
#define F_B3    37760          // [128]
#define F_PT    37888          // [20][132] protein type table (+b1 folded)
#define F_LT    40528          // [16][132] ligand type table
#define F_META  42640          // [4][64] ints (pt | lt<<8 per row)
#define F_INFO  42896          // 17 ints: cnt8[8], tile prefix[9]
#define SMEM_FLOATS 42913
#define SMEM_BYTES (SMEM_FLOATS * 4)   // 171,652 bytes
// Tail-finalize overlays (dead weight region, float indices):
#define F_WR1  0               // [128][128] fp32 Wr1 (64 KB)
#define F_REPR 16384           // [8][128]
#define F_OUT  17408           // [8]

// Global scratch. Zero-initialized at module load; the last CTA restores the
// zeroed invariant at the end of every launch -> deterministic across calls.
__device__ float gAccum[BB * HH];
__device__ int   gListCnt[BB];
__device__ int   gDone;
__device__ uint2 gList[BB * LIST_CAP];   // {meta, dist-bits}, 2 MB

// 64-thread named barrier per pipeline (ids 1..4)
#define PBAR(p) asm volatile("bar.sync %0, 64;" :: "r"((p) + 1) : "memory")

// ---------------------------------------------------------------------------
__device__ __forceinline__ void mma_f16(float c[4], const uint32_t a[4],
                                        uint32_t b0, uint32_t b1) {
    asm volatile(
        "mma.sync.aligned.m16n8k16.row.col.f32.f16.f16.f32 "
        "{%0,%1,%2,%3}, {%4,%5,%6,%7}, {%8,%9}, {%0,%1,%2,%3};"
        : "+f"(c[0]), "+f"(c[1]), "+f"(c[2]), "+f"(c[3])
        : "r"(a[0]), "r"(a[1]), "r"(a[2]), "r"(a[3]), "r"(b0), "r"(b1));
}

// Warp-level GEMM: acc[4][8][4] += A[0..64, :K] @ W[ncol0..+64][k]^T
template<int KSTEPS, int WPITCH>
__device__ __forceinline__ void layer_mma4(const __half* __restrict__ hA,
                                           const __half* __restrict__ Wb,
                                           int ncol0, int lane,
                                           float acc[4][8][4]) {
    const int gr = lane >> 2, tig = lane & 3;
    #pragma unroll
    for (int ks = 0; ks < KSTEPS; ks++) {
        uint32_t a[4][4];
        #pragma unroll
        for (int mt = 0; mt < 4; mt++) {
            const __half* base = hA + (mt * 16 + gr) * H_PITCH_H
                                    + ks * 16 + 2 * tig;
            a[mt][0] = *(const uint32_t*)(base);
            a[mt][1] = *(const uint32_t*)(base + 8 * H_PITCH_H);
            a[mt][2] = *(const uint32_t*)(base + 8);
            a[mt][3] = *(const uint32_t*)(base + 8 * H_PITCH_H + 8);
        }
        #pragma unroll
        for (int nt = 0; nt < 8; nt++) {
            const __half* bp = Wb + (ncol0 + nt * 8 + gr) * WPITCH
                                  + ks * 16 + 2 * tig;
            uint32_t b0 = *(const uint32_t*)(bp);
            uint32_t b1 = *(const uint32_t*)(bp + 8);
            #pragma unroll
            for (int mt = 0; mt < 4; mt++)
                mma_f16(acc[mt][nt], a[mt], b0, b1);
        }
    }
}

// ---------------------------------------------------------------------------
// Compact: find valid pairs, append {types, dist} to per-complex lists.
// Ligand positions cached in SMEM; block-aggregated global atomics.
// ---------------------------------------------------------------------------
__global__ __launch_bounds__(256)
void compact_kernel(const float* __restrict__ ppos, const float* __restrict__ lpos,
                    const int* __restrict__ ptype, const int* __restrict__ ltype) {
    __shared__ float slig[LL * 3];
    __shared__ int wbase[8];
    __shared__ int blockBase;
    const int b   = blockIdx.x >> 7;        // 128 blocks per complex
    const int blk = blockIdx.x & 127;       // 4 protein atoms per block
    if (threadIdx.x < LL * 3)
        slig[threadIdx.x] = lpos[b * LL * 3 + threadIdx.x];
    __syncthreads();

    const int ll = threadIdx.x & 63;
    const int pl = blk * 4 + (threadIdx.x >> 6);
    const float* pp = ppos + (size_t)(b * PP + pl) * 3;
    const float dx = pp[0] - slig[ll * 3];
    const float dy = pp[1] - slig[ll * 3 + 1];
    const float dz = pp[2] - slig[ll * 3 + 2];
    const float dist = sqrtf(dx * dx + dy * dy + dz * dz);
    const int valid = dist < 8.0f;
    const unsigned bal = __ballot_sync(0xffffffffu, valid);
    const int lane = threadIdx.x & 31;
    const int wid = threadIdx.x >> 5;
    if (lane == 0) wbase[wid] = __popc(bal);
    __syncthreads();
    if (threadIdx.x == 0) {
        int tot = 0;
        #pragma unroll
        for (int i = 0; i < 8; i++) { int c = wbase[i]; wbase[i] = tot; tot += c; }
        blockBase = atomicAdd(&gListCnt[b], tot);
    }
    __syncthreads();
    if (valid) {
        const int off = blockBase + wbase[wid] + __popc(bal & ((1u << lane) - 1u));
        const uint32_t meta = (uint32_t)ptype[b * PP + pl]
                            | ((uint32_t)ltype[b * LL + ll] << 8);
        gList[b * LIST_CAP + off] = make_uint2(meta, __float_as_uint(dist));
    }
}

// ---------------------------------------------------------------------------
// Main: 64-pair tiles through the 3-layer MLP; four 2-warp pipelines per CTA.
// The LAST CTA to finish also runs the readout MLP and resets global scratch.
// ---------------------------------------------------------------------------
__global__ __launch_bounds__(256, 1)
void main_kernel(const float* __restrict__ pemb, const float* __restrict__ lemb,
                 const float* __restrict__ W1, const float* __restrict__ b1,
                 const float* __restrict__ W2, const float* __restrict__ b2,
                 const float* __restrict__ W3, const float* __restrict__ b3,
                 const float* __restrict__ Wr1, const float* __restrict__ br1,
                 const float* __restrict__ Wr2, const float* __restrict__ br2,
                 float* __restrict__ out) {
    extern __shared__ float sm[];
    __half* smh = (__half*)sm;
    __half* sW1r = smh + H_W1R;
    __half* sW2  = smh + H_W2;
    __half* sW3  = smh + H_W3;
    float* sPT = sm + F_PT;
    float* sLT = sm + F_LT;
    int* sInfo = (int*)(sm + F_INFO);   // [0..7]=cnt, [8..16]=tile prefix

    const int tid = threadIdx.x;
    const int w = tid >> 5;
    const int lane = tid & 31;
    const int gr = lane >> 2, tig = lane & 3;
    const int p = w >> 1;              // pipeline 0..3
    const int lw = w & 1;              // warp within pipeline
    const int p_tid = tid & 63;

    __half* sH     = smh + H_H + p * 8704;     // [64][136] halves
    float*  sMskP  = sm + F_MSK + p * 64;
    int*    sMetaP = (int*)(sm + F_META) + p * 64;

    // ---- Prologue: stage weights fp16 n-major ----
    for (int idx = tid; idx < 32 * 128; idx += 256) {
        int k = idx >> 7, n = idx & 127;
        sW1r[n * W1R_PITCH_H + k] = __float2half_rn(W1[(256 + k) * 128 + n]);
    }
    for (int idx = tid; idx < 128 * 128; idx += 256) {
        int k = idx >> 7, n = idx & 127;
        sW2[n * W_PITCH_H + k] = __float2half_rn(W2[k * 128 + n]);
        sW3[n * W_PITCH_H + k] = __float2half_rn(W3[k * 128 + n]);
    }
    if (tid < 128) { sm[F_B2 + tid] = b2[tid]; sm[F_B3 + tid] = b3[tid]; }

    {   // type tables into SMEM: Ptab = pemb@W1[0:128]+b1, Ltab = lemb@W1[128:256]
        const int c = tid & 127;
        if (tid < 128) {
            float tab[NPT];
            #pragma unroll
            for (int t = 0; t < NPT; t++) tab[t] = 0.f;
            for (int k = 0; k < 128; k++) {
                float wv = W1[k * 128 + c];
                #pragma unroll
                for (int t = 0; t < NPT; t++) tab[t] += wv * pemb[t * 128 + k];
            }
            float bb = b1[c];
            #pragma unroll
            for (int t = 0; t < NPT; t++) sPT[t * 132 + c] = tab[t] + bb;
        } else {
            float tab[NLT];
            #pragma unroll
            for (int t = 0; t < NLT; t++) tab[t] = 0.f;
            for (int k = 0; k < 128; k++) {
                float wv = W1[(128 + k) * 128 + c];
                #pragma unroll
                for (int t = 0; t < NLT; t++) tab[t] += wv * lemb[t * 128 + k];
            }
            #pragma unroll
            for (int t = 0; t < NLT; t++) sLT[t * 132 + c] = tab[t];
        }
    }
    if (tid == 0) {
        int acc = 0;
        sInfo[8] = 0;
        #pragma unroll
        for (int b = 0; b < BB; b++) {
            int c = gListCnt[b];
            sInfo[b] = c;
            acc += (c + 63) >> 6;      // 64-pair tiles
            sInfo[9 + b] = acc;
        }
    }
    __syncthreads();

    const int ncol0 = lw * 64;

    float accum[16];
    #pragma unroll
    for (int j = 0; j < 16; j++) accum[j] = 0.f;
    int cur_b = -1;

    const float invw  = 1.0f / (0.125f + 1e-8f);
    const float cstep = 8.0f / 31.0f;
    const int totTiles = sInfo[16];
    const int gid = blockIdx.x * 4 + p;

    auto flush = [&]() {
        #pragma unroll
        for (int j = 0; j < 16; j++) {
            accum[j] += __shfl_xor_sync(0xffffffffu, accum[j], 4);
            accum[j] += __shfl_xor_sync(0xffffffffu, accum[j], 8);
            accum[j] += __shfl_xor_sync(0xffffffffu, accum[j], 16);
        }
        if (lane < 4) {
            #pragma unroll
            for (int nt = 0; nt < 8; nt++) {
                atomicAdd(&gAccum[cur_b * HH + ncol0 + nt * 8 + lane * 2],     accum[nt * 2]);
                atomicAdd(&gAccum[cur_b * HH + ncol0 + nt * 8 + lane * 2 + 1], accum[nt * 2 + 1]);
            }
        }
        #pragma unroll
        for (int j = 0; j < 16; j++) accum[j] = 0.f;
    };

    for (int tl = gid; tl < totTiles; tl += 4 * GRIDX) {
        int b = 0;
        while (tl >= sInfo[9 + b]) b++;
        const int ti = tl - sInfo[8 + b];
        const int cntb = sInfo[b];
        if (b != cur_b) {
            if (cur_b >= 0) flush();
            cur_b = b;
        }

        PBAR(p);   // protect sH/sMsk/sMeta from this pipeline's previous readers

        // ---- Phase 1: load compacted pair record, radial basis -> sH ----
        {
            const int idx = ti * 64 + p_tid;
            uint2 e;
            float mk;
            if (idx < cntb) { e = gList[b * LIST_CAP + idx]; mk = 1.0f; }
            else            { e = make_uint2(0u, __float_as_uint(1e9f)); mk = 0.0f; }
            const float dist = __uint_as_float(e.y);
            sMskP[p_tid] = mk;
            sMetaP[p_tid] = (int)e.x;
            float rbv[32];
            #pragma unroll
            for (int j = 0; j < 32; j++) {
                const float tt = (dist - (float)j * cstep) * invw;
                rbv[j] = __expf(-0.5f * tt * tt);
            }
            __half* rowp = sH + p_tid * H_PITCH_H;
            #pragma unroll
            for (int j = 0; j < 16; j++)
                *(__half2*)(rowp + 2 * j) = __floats2half2_rn(rbv[2 * j], rbv[2 * j + 1]);
        }
        PBAR(p);

        float acc[4][8][4];

        // ---- Layer 1: rb @ W1r ----
        #pragma unroll
        for (int mt = 0; mt < 4; mt++)
            #pragma unroll
            for (int nt = 0; nt < 8; nt++)
                #pragma unroll
                for (int j = 0; j < 4; j++) acc[mt][nt][j] = 0.f;
        layer_mma4<2, W1R_PITCH_H>(sH, sW1r, ncol0, lane, acc);
        PBAR(p);

        // ---- Epilogue 1: + Ptab[row] + Ltab[row], relu -> sH ----
        {
            #pragma unroll
            for (int mt = 0; mt < 4; mt++) {
                const int r1 = mt * 16 + gr;
                const int r2 = r1 + 8;
                const int m1 = sMetaP[r1], m2 = sMetaP[r2];
                const float* PT1 = sPT + (m1 & 0xff) * 132;
                const float* LT1 = sLT + (m1 >> 8) * 132;
                const float* PT2 = sPT + (m2 & 0xff) * 132;
                const float* LT2 = sLT + (m2 >> 8) * 132;
                #pragma unroll
                for (int nt = 0; nt < 8; nt++) {
                    const int c = ncol0 + nt * 8 + tig * 2;
                    const float2 p1 = *(const float2*)(PT1 + c);
                    const float2 l1 = *(const float2*)(LT1 + c);
                    const float2 p2 = *(const float2*)(PT2 + c);
                    const float2 l2 = *(const float2*)(LT2 + c);
                    *(__half2*)(sH + r1 * H_PITCH_H + c) = __floats2half2_rn(
                        fmaxf(acc[mt][nt][0] + p1.x + l1.x, 0.f),
                        fmaxf(acc[mt][nt][1] + p1.y + l1.y, 0.f));
                    *(__half2*)(sH + r2 * H_PITCH_H + c) = __floats2half2_rn(
                        fmaxf(acc[mt][nt][2] + p2.x + l2.x, 0.f),
                        fmaxf(acc[mt][nt][3] + p2.y + l2.y, 0.f));
                }
            }
        }
        PBAR(p);

        // ---- Layer 2 ----
        #pragma unroll
        for (int mt = 0; mt < 4; mt++)
            #pragma unroll
            for (int nt = 0; nt < 8; nt++)
                #pragma unroll
                for (int j = 0; j < 4; j++) acc[mt][nt][j] = 0.f;
        layer_mma4<8, W_PITCH_H>(sH, sW2, ncol0, lane, acc);
        PBAR(p);
        {
            #pragma unroll
            for (int mt = 0; mt < 4; mt++) {
                const int r1 = mt * 16 + gr;
                const int r2 = r1 + 8;
                #pragma unroll
                for (int nt = 0; nt < 8; nt++) {
                    const int c = ncol0 + nt * 8 + tig * 2;
                    const float b0 = sm[F_B2 + c], b1v = sm[F_B2 + c + 1];
                    *(__half2*)(sH + r1 * H_PITCH_H + c) = __floats2half2_rn(
                        fmaxf(acc[mt][nt][0] + b0,  0.f),
                        fmaxf(acc[mt][nt][1] + b1v, 0.f));
                    *(__half2*)(sH + r2 * H_PITCH_H + c) = __floats2half2_rn(
                        fmaxf(acc[mt][nt][2] + b0,  0.f),
                        fmaxf(acc[mt][nt][3] + b1v, 0.f));
                }
            }
        }
        PBAR(p);

        // ---- Layer 3 + masked register accumulation ----
        #pragma unroll
        for (int mt = 0; mt < 4; mt++)
            #pragma unroll
            for (int nt = 0; nt < 8; nt++)
                #pragma unroll
                for (int j = 0; j < 4; j++) acc[mt][nt][j] = 0.f;
        layer_mma4<8, W_PITCH_H>(sH, sW3, ncol0, lane, acc);
        {
            #pragma unroll
            for (int mt = 0; mt < 4; mt++) {
                const int r1 = mt * 16 + gr;
                const int r2 = r1 + 8;
                const float mk1 = sMskP[r1], mk2 = sMskP[r2];
                #pragma unroll
                for (int nt = 0; nt < 8; nt++) {
                    const int c = ncol0 + nt * 8 + tig * 2;
                    const float b0 = sm[F_B3 + c], b1v = sm[F_B3 + c + 1];
                    accum[nt * 2]     += mk1 * fmaxf(acc[mt][nt][0] + b0,  0.f)
                                       + mk2 * fmaxf(acc[mt][nt][2] + b0,  0.f);
                    accum[nt * 2 + 1] += mk1 * fmaxf(acc[mt][nt][1] + b1v, 0.f)
                                       + mk2 * fmaxf(acc[mt][nt][3] + b1v, 0.f);
                }
            }
        }
    }
    if (cur_b >= 0) flush();

    // ---- Tail: last CTA to arrive runs the readout MLP + scratch reset ----
    __threadfence();
    __shared__ int isLast;
    __syncthreads();           // all pipelines done flushing before arrive
    if (tid == 0) isLast = (atomicAdd(&gDone, 1) == GRIDX - 1);
    __syncthreads();
    if (!isLast) return;
    __threadfence();           // acquire all CTAs' gAccum writes

    float* sWr1  = sm + F_WR1;     // overlays dead fp16 weight region
    float* sRepr = sm + F_REPR;
    float* sOut  = sm + F_OUT;
    for (int i = tid; i < HH * HH; i += 256) sWr1[i] = Wr1[i];
    if (tid < 8) sOut[tid] = 0.f;
    for (int i = tid; i < BB * HH; i += 256)
        sRepr[i] = gAccum[i] / fmaxf((float)sInfo[i >> 7], 1.0f);
    __syncthreads();
    #pragma unroll
    for (int j = 0; j < 4; j++) {
        const int idx = tid + 256 * j;   // 0..1023 = (b, c)
        const int b = idx >> 7, c = idx & 127;
        float v = br1[c];
        const float* rp = sRepr + b * HH;
        #pragma unroll 8
        for (int k = 0; k < HH; k++) v += rp[k] * sWr1[k * HH + c];
        v = fmaxf(v, 0.f) * Wr2[c];
        atomicAdd(&sOut[b], v);
    }
    __syncthreads();
    if (tid < 8) {
        out[tid] = (sInfo[tid] > 0) ? (sOut[tid] + br2[0]) : 0.0f;
        gListCnt[tid] = 0;
    }
    for (int i = tid; i < BB * HH; i += 256) gAccum[i] = 0.f;
    if (tid == 0) gDone = 0;
}

// ---------------------------------------------------------------------------
extern "C" void kernel_launch(void* const* d_in, const int* in_sizes, int n_in,
                              void* d_out, int out_size) {
    const float* ppos = (const float*)d_in[0];
    const float* lpos = (const float*)d_in[1];
    const float* pemb = (const float*)d_in[2];
    const float* lemb = (const float*)d_in[3];
    const float* W1   = (const float*)d_in[4];
    const float* b1   = (const float*)d_in[5];
    const float* W2   = (const float*)d_in[6];
    const float* b2   = (const float*)d_in[7];
    const float* W3   = (const float*)d_in[8];
    const float* b3   = (const float*)d_in[9];
    const float* Wr1  = (const float*)d_in[10];
    const float* br1  = (const float*)d_in[11];
    const float* Wr2  = (const float*)d_in[12];
    const float* br2  = (const float*)d_in[13];
    const int*   pt   = (const int*)d_in[14];
    const int*   lt   = (const int*)d_in[15];
    float* out = (float*)d_out;

    cudaFuncSetAttribute(main_kernel,
                         cudaFuncAttributeMaxDynamicSharedMemorySize, SMEM_BYTES);

    compact_kernel<<<BB * 128, 256>>>(ppos, lpos, pt, lt);
    main_kernel<<<GRIDX, 256, SMEM_BYTES>>>(pemb, lemb, W1, b1, W2, b2, W3, b3,
                                            Wr1, br1, Wr2, br2, out);
}

// round 17
// speedup vs baseline: 1.2952x; 1.2952x over previous
#include <cuda_runtime.h>
#include <cuda_fp16.h>
#include <cstdint>
#include <math.h>

// Problem constants
#define BB 8
#define PP 512
#define LL 64
#define HH 128
#define NPT 20
#define NLT 16
#define GRIDX 148
#define LIST_CAP 32768         // P*L pairs per complex (worst case)

// SMEM layout. Half regions first (indices in halves), float tail after.
#define W1R_PITCH_H 40
#define W_PITCH_H   136
#define H_PITCH_H   136
#define H_W1R 0                // 128*40  = 5120 halves
#define H_W2  5120             // 128*136 = 17408
#define H_W3  22528
#define H_H   39936            // 4 pipeline buffers [64][136] halves (8704 each)
#define F_MSK   37376          // [4][64] floats
#define F_B2    37632          // [128]
#define F_B3    37760          // [128]
#define F_PT    37888          // [20][132] protein type table (+b1 folded)
#define F_LT    40528          // [16][132] ligand type table
#define F_META  42640          // [4][64] ints (pt | lt<<8 per row)
#define F_INFO  42896          // 17 ints: cnt8[8], tile prefix[9]
#define SMEM_FLOATS 42913
#define SMEM_BYTES (SMEM_FLOATS * 4)   // 171,652 bytes

// Global scratch. Zero-initialized at module load; finalize_kernel restores the
// zeroed invariant at the end of every launch -> deterministic across calls.
__device__ float gAccum[BB * HH];
__device__ int   gListCnt[BB];
__device__ uint2 gList[BB * LIST_CAP];   // {meta, dist-bits}, 2 MB

// 64-thread named barrier per pipeline (ids 1..4)
#define PBAR(p) asm volatile("bar.sync %0, 64;" :: "r"((p) + 1) : "memory")

// ---------------------------------------------------------------------------
__device__ __forceinline__ void mma_f16(float c[4], const uint32_t a[4],
                                        uint32_t b0, uint32_t b1) {
    asm volatile(
        "mma.sync.aligned.m16n8k16.row.col.f32.f16.f16.f32 "
        "{%0,%1,%2,%3}, {%4,%5,%6,%7}, {%8,%9}, {%0,%1,%2,%3};"
        : "+f"(c[0]), "+f"(c[1]), "+f"(c[2]), "+f"(c[3])
        : "r"(a[0]), "r"(a[1]), "r"(a[2]), "r"(a[3]), "r"(b0), "r"(b1));
}

// Warp-level GEMM: acc[4][8][4] += A[0..64, :K] @ W[ncol0..+64][k]^T
template<int KSTEPS, int WPITCH>
__device__ __forceinline__ void layer_mma4(const __half* __restrict__ hA,
                                           const __half* __restrict__ Wb,
                                           int ncol0, int lane,
                                           float acc[4][8][4]) {
    const int gr = lane >> 2, tig = lane & 3;
    #pragma unroll
    for (int ks = 0; ks < KSTEPS; ks++) {
        uint32_t a[4][4];
        #pragma unroll
        for (int mt = 0; mt < 4; mt++) {
            const __half* base = hA + (mt * 16 + gr) * H_PITCH_H
                                    + ks * 16 + 2 * tig;
            a[mt][0] = *(const uint32_t*)(base);
            a[mt][1] = *(const uint32_t*)(base + 8 * H_PITCH_H);
            a[mt][2] = *(const uint32_t*)(base + 8);
            a[mt][3] = *(const uint32_t*)(base + 8 * H_PITCH_H + 8);
        }
        #pragma unroll
        for (int nt = 0; nt < 8; nt++) {
            const __half* bp = Wb + (ncol0 + nt * 8 + gr) * WPITCH
                                  + ks * 16 + 2 * tig;
            uint32_t b0 = *(const uint32_t*)(bp);
            uint32_t b1 = *(const uint32_t*)(bp + 8);
            #pragma unroll
            for (int mt = 0; mt < 4; mt++)
                mma_f16(acc[mt][nt], a[mt], b0, b1);
        }
    }
}

// ---------------------------------------------------------------------------
// Compact: find valid pairs, append {types, dist} to per-complex lists.
// Ligand positions cached in SMEM; block-aggregated global atomics.
// ---------------------------------------------------------------------------
__global__ __launch_bounds__(256)
void compact_kernel(const float* __restrict__ ppos, const float* __restrict__ lpos,
                    const int* __restrict__ ptype, const int* __restrict__ ltype) {
    __shared__ float slig[LL * 3];
    __shared__ int wbase[8];
    __shared__ int blockBase;
    const int b   = blockIdx.x >> 7;        // 128 blocks per complex
    const int blk = blockIdx.x & 127;       // 4 protein atoms per block
    if (threadIdx.x < LL * 3)
        slig[threadIdx.x] = lpos[b * LL * 3 + threadIdx.x];
    __syncthreads();

    const int ll = threadIdx.x & 63;
    const int pl = blk * 4 + (threadIdx.x >> 6);
    const float* pp = ppos + (size_t)(b * PP + pl) * 3;
    const float dx = pp[0] - slig[ll * 3];
    const float dy = pp[1] - slig[ll * 3 + 1];
    const float dz = pp[2] - slig[ll * 3 + 2];
    const float dist = sqrtf(dx * dx + dy * dy + dz * dz);
    const int valid = dist < 8.0f;
    const unsigned bal = __ballot_sync(0xffffffffu, valid);
    const int lane = threadIdx.x & 31;
    const int wid = threadIdx.x >> 5;
    if (lane == 0) wbase[wid] = __popc(bal);
    __syncthreads();
    if (threadIdx.x == 0) {
        int tot = 0;
        #pragma unroll
        for (int i = 0; i < 8; i++) { int c = wbase[i]; wbase[i] = tot; tot += c; }
        blockBase = atomicAdd(&gListCnt[b], tot);
    }
    __syncthreads();
    if (valid) {
        const int off = blockBase + wbase[wid] + __popc(bal & ((1u << lane) - 1u));
        const uint32_t meta = (uint32_t)ptype[b * PP + pl]
                            | ((uint32_t)ltype[b * LL + ll] << 8);
        gList[b * LIST_CAP + off] = make_uint2(meta, __float_as_uint(dist));
    }
}

// ---------------------------------------------------------------------------
// Main: 64-pair tiles through the 3-layer MLP; FOUR 2-warp pipelines per CTA
// (byte-identical to the R13 engine).
// ---------------------------------------------------------------------------
__global__ __launch_bounds__(256, 1)
void main_kernel(const float* __restrict__ pemb, const float* __restrict__ lemb,
                 const float* __restrict__ W1, const float* __restrict__ b1,
                 const float* __restrict__ W2, const float* __restrict__ b2,
                 const float* __restrict__ W3, const float* __restrict__ b3) {
    extern __shared__ float sm[];
    __half* smh = (__half*)sm;
    __half* sW1r = smh + H_W1R;
    __half* sW2  = smh + H_W2;
    __half* sW3  = smh + H_W3;
    float* sPT = sm + F_PT;
    float* sLT = sm + F_LT;
    int* sInfo = (int*)(sm + F_INFO);   // [0..7]=cnt, [8..16]=tile prefix

    const int tid = threadIdx.x;
    const int w = tid >> 5;
    const int lane = tid & 31;
    const int gr = lane >> 2, tig = lane & 3;
    const int p = w >> 1;              // pipeline 0..3
    const int lw = w & 1;              // warp within pipeline
    const int p_tid = tid & 63;

    __half* sH     = smh + H_H + p * 8704;     // [64][136] halves
    float*  sMskP  = sm + F_MSK + p * 64;
    int*    sMetaP = (int*)(sm + F_META) + p * 64;

    // ---- Prologue: stage weights fp16 n-major ----
    for (int idx = tid; idx < 32 * 128; idx += 256) {
        int k = idx >> 7, n = idx & 127;
        sW1r[n * W1R_PITCH_H + k] = __float2half_rn(W1[(256 + k) * 128 + n]);
    }
    for (int idx = tid; idx < 128 * 128; idx += 256) {
        int k = idx >> 7, n = idx & 127;
        sW2[n * W_PITCH_H + k] = __float2half_rn(W2[k * 128 + n]);
        sW3[n * W_PITCH_H + k] = __float2half_rn(W3[k * 128 + n]);
    }
    if (tid < 128) { sm[F_B2 + tid] = b2[tid]; sm[F_B3 + tid] = b3[tid]; }

    {   // type tables into SMEM: Ptab = pemb@W1[0:128]+b1, Ltab = lemb@W1[128:256]
        const int c = tid & 127;
        if (tid < 128) {
            float tab[NPT];
            #pragma unroll
            for (int t = 0; t < NPT; t++) tab[t] = 0.f;
            for (int k = 0; k < 128; k++) {
                float wv = W1[k * 128 + c];
                #pragma unroll
                for (int t = 0; t < NPT; t++) tab[t] += wv * pemb[t * 128 + k];
            }
            float bb = b1[c];
            #pragma unroll
            for (int t = 0; t < NPT; t++) sPT[t * 132 + c] = tab[t] + bb;
        } else {
            float tab[NLT];
            #pragma unroll
            for (int t = 0; t < NLT; t++) tab[t] = 0.f;
            for (int k = 0; k < 128; k++) {
                float wv = W1[(128 + k) * 128 + c];
                #pragma unroll
                for (int t = 0; t < NLT; t++) tab[t] += wv * lemb[t * 128 + k];
            }
            #pragma unroll
            for (int t = 0; t < NLT; t++) sLT[t * 132 + c] = tab[t];
        }
    }
    if (tid == 0) {
        int acc = 0;
        sInfo[8] = 0;
        #pragma unroll
        for (int b = 0; b < BB; b++) {
            int c = gListCnt[b];
            sInfo[b] = c;
            acc += (c + 63) >> 6;      // 64-pair tiles
            sInfo[9 + b] = acc;
        }
    }
    __syncthreads();

    const int ncol0 = lw * 64;

    float accum[16];
    #pragma unroll
    for (int j = 0; j < 16; j++) accum[j] = 0.f;
    int cur_b = -1;

    const float invw  = 1.0f / (0.125f + 1e-8f);
    const float cstep = 8.0f / 31.0f;
    const int totTiles = sInfo[16];
    const int gid = blockIdx.x * 4 + p;

    auto flush = [&]() {
        #pragma unroll
        for (int j = 0; j < 16; j++) {
            accum[j] += __shfl_xor_sync(0xffffffffu, accum[j], 4);
            accum[j] += __shfl_xor_sync(0xffffffffu, accum[j], 8);
            accum[j] += __shfl_xor_sync(0xffffffffu, accum[j], 16);
        }
        if (lane < 4) {
            #pragma unroll
            for (int nt = 0; nt < 8; nt++) {
                atomicAdd(&gAccum[cur_b * HH + ncol0 + nt * 8 + lane * 2],     accum[nt * 2]);
                atomicAdd(&gAccum[cur_b * HH + ncol0 + nt * 8 + lane * 2 + 1], accum[nt * 2 + 1]);
            }
        }
        #pragma unroll
        for (int j = 0; j < 16; j++) accum[j] = 0.f;
    };

    for (int tl = gid; tl < totTiles; tl += 4 * GRIDX) {
        int b = 0;
        while (tl >= sInfo[9 + b]) b++;
        const int ti = tl - sInfo[8 + b];
        const int cntb = sInfo[b];
        if (b != cur_b) {
            if (cur_b >= 0) flush();
            cur_b = b;
        }

        PBAR(p);   // protect sH/sMsk/sMeta from this pipeline's previous readers

        // ---- Phase 1: load compacted pair record, radial basis -> sH ----
        {
            const int idx = ti * 64 + p_tid;
            uint2 e;
            float mk;
            if (idx < cntb) { e = gList[b * LIST_CAP + idx]; mk = 1.0f; }
            else            { e = make_uint2(0u, __float_as_uint(1e9f)); mk = 0.0f; }
            const float dist = __uint_as_float(e.y);
            sMskP[p_tid] = mk;
            sMetaP[p_tid] = (int)e.x;
            float rbv[32];
            #pragma unroll
            for (int j = 0; j < 32; j++) {
                const float tt = (dist - (float)j * cstep) * invw;
                rbv[j] = __expf(-0.5f * tt * tt);
            }
            __half* rowp = sH + p_tid * H_PITCH_H;
            #pragma unroll
            for (int j = 0; j < 16; j++)
                *(__half2*)(rowp + 2 * j) = __floats2half2_rn(rbv[2 * j], rbv[2 * j + 1]);
        }
        PBAR(p);

        float acc[4][8][4];

        // ---- Layer 1: rb @ W1r ----
        #pragma unroll
        for (int mt = 0; mt < 4; mt++)
            #pragma unroll
            for (int nt = 0; nt < 8; nt++)
                #pragma unroll
                for (int j = 0; j < 4; j++) acc[mt][nt][j] = 0.f;
        layer_mma4<2, W1R_PITCH_H>(sH, sW1r, ncol0, lane, acc);
        PBAR(p);

        // ---- Epilogue 1: + Ptab[row] + Ltab[row], relu -> sH ----
        {
            #pragma unroll
            for (int mt = 0; mt < 4; mt++) {
                const int r1 = mt * 16 + gr;
                const int r2 = r1 + 8;
                const int m1 = sMetaP[r1], m2 = sMetaP[r2];
                const float* PT1 = sPT + (m1 & 0xff) * 132;
                const float* LT1 = sLT + (m1 >> 8) * 132;
                const float* PT2 = sPT + (m2 & 0xff) * 132;
                const float* LT2 = sLT + (m2 >> 8) * 132;
                #pragma unroll
                for (int nt = 0; nt < 8; nt++) {
                    const int c = ncol0 + nt * 8 + tig * 2;
                    const float2 p1 = *(const float2*)(PT1 + c);
                    const float2 l1 = *(const float2*)(LT1 + c);
                    const float2 p2 = *(const float2*)(PT2 + c);
                    const float2 l2 = *(const float2*)(LT2 + c);
                    *(__half2*)(sH + r1 * H_PITCH_H + c) = __floats2half2_rn(
                        fmaxf(acc[mt][nt][0] + p1.x + l1.x, 0.f),
                        fmaxf(acc[mt][nt][1] + p1.y + l1.y, 0.f));
                    *(__half2*)(sH + r2 * H_PITCH_H + c) = __floats2half2_rn(
                        fmaxf(acc[mt][nt][2] + p2.x + l2.x, 0.f),
                        fmaxf(acc[mt][nt][3] + p2.y + l2.y, 0.f));
                }
            }
        }
        PBAR(p);

        // ---- Layer 2 ----
        #pragma unroll
        for (int mt = 0; mt < 4; mt++)
            #pragma unroll
            for (int nt = 0; nt < 8; nt++)
                #pragma unroll
                for (int j = 0; j < 4; j++) acc[mt][nt][j] = 0.f;
        layer_mma4<8, W_PITCH_H>(sH, sW2, ncol0, lane, acc);
        PBAR(p);
        {
            #pragma unroll
            for (int mt = 0; mt < 4; mt++) {
                const int r1 = mt * 16 + gr;
                const int r2 = r1 + 8;
                #pragma unroll
                for (int nt = 0; nt < 8; nt++) {
                    const int c = ncol0 + nt * 8 + tig * 2;
                    const float b0 = sm[F_B2 + c], b1v = sm[F_B2 + c + 1];
                    *(__half2*)(sH + r1 * H_PITCH_H + c) = __floats2half2_rn(
                        fmaxf(acc[mt][nt][0] + b0,  0.f),
                        fmaxf(acc[mt][nt][1] + b1v, 0.f));
                    *(__half2*)(sH + r2 * H_PITCH_H + c) = __floats2half2_rn(
                        fmaxf(acc[mt][nt][2] + b0,  0.f),
                        fmaxf(acc[mt][nt][3] + b1v, 0.f));
                }
            }
        }
        PBAR(p);

        // ---- Layer 3 + masked register accumulation ----
        #pragma unroll
        for (int mt = 0; mt < 4; mt++)
            #pragma unroll
            for (int nt = 0; nt < 8; nt++)
                #pragma unroll
                for (int j = 0; j < 4; j++) acc[mt][nt][j] = 0.f;
        layer_mma4<8, W_PITCH_H>(sH, sW3, ncol0, lane, acc);
        {
            #pragma unroll
            for (int mt = 0; mt < 4; mt++) {
                const int r1 = mt * 16 + gr;
                const int r2 = r1 + 8;
                const float mk1 = sMskP[r1], mk2 = sMskP[r2];
                #pragma unroll
                for (int nt = 0; nt < 8; nt++) {
                    const int c = ncol0 + nt * 8 + tig * 2;
                    const float b0 = sm[F_B3 + c], b1v = sm[F_B3 + c + 1];
                    accum[nt * 2]     += mk1 * fmaxf(acc[mt][nt][0] + b0,  0.f)
                                       + mk2 * fmaxf(acc[mt][nt][2] + b0,  0.f);
                    accum[nt * 2 + 1] += mk1 * fmaxf(acc[mt][nt][1] + b1v, 0.f)
                                       + mk2 * fmaxf(acc[mt][nt][3] + b1v, 0.f);
                }
            }
        }
    }
    if (cur_b >= 0) flush();
}

// ---------------------------------------------------------------------------
// Finalize: readout MLP per complex (1024 thr: 8 k-slices x 128 cols), then
// reset the global accumulators to restore the zeroed-state invariant.
// ---------------------------------------------------------------------------
__global__ __launch_bounds__(1024)
void finalize_kernel(const float* __restrict__ Wr1,
                     const float* __restrict__ br1,
                     const float* __restrict__ Wr2,
                     const float* __restrict__ br2,
                     float* __restrict__ out) {
    const int b = blockIdx.x;
    const int t = threadIdx.x;   // 0..1023
    const int c = t & 127;
    const int s = t >> 7;        // k-slice 0..7
    __shared__ float repr[HH];
    __shared__ float part[8][HH];
    __shared__ float red[HH];
    const int cnt = gListCnt[b];
    if (s == 0) repr[c] = gAccum[b * HH + c] / fmaxf((float)cnt, 1.0f);
    __syncthreads();
    float p = 0.f;
    const int k0 = s * 16;
    #pragma unroll
    for (int k = 0; k < 16; k++) p += repr[k0 + k] * Wr1[(k0 + k) * HH + c];
    part[s][c] = p;
    __syncthreads();
    if (s == 0) {
        float v = br1[c];
        #pragma unroll
        for (int j = 0; j < 8; j++) v += part[j][c];
        v = fmaxf(v, 0.f);
        red[c] = v * Wr2[c];
    }
    __syncthreads();
    for (int st = 64; st > 0; st >>= 1) {
        if (t < st) red[t] += red[t + st];
        __syncthreads();
    }
    if (t == 0) out[b] = (cnt > 0) ? (red[0] + br2[0]) : 0.0f;
    // Restore zeroed invariant for the next launch.
    if (s == 0) gAccum[b * HH + c] = 0.f;
    if (t == 0) gListCnt[b] = 0;
}

// ---------------------------------------------------------------------------
extern "C" void kernel_launch(void* const* d_in, const int* in_sizes, int n_in,
                              void* d_out, int out_size) {
    const float* ppos = (const float*)d_in[0];
    const float* lpos = (const float*)d_in[1];
    const float* pemb = (const float*)d_in[2];
    const float* lemb = (const float*)d_in[3];
    const float* W1   = (const float*)d_in[4];
    const float* b1   = (const float*)d_in[5];
    const float* W2   = (const float*)d_in[6];
    const float* b2   = (const float*)d_in[7];
    const float* W3   = (const float*)d_in[8];
    const float* b3   = (const float*)d_in[9];
    const float* Wr1  = (const float*)d_in[10];
    const float* br1  = (const float*)d_in[11];
    const float* Wr2  = (const float*)d_in[12];
    const float* br2  = (const float*)d_in[13];
    const int*   pt   = (const int*)d_in[14];
    const int*   lt   = (const int*)d_in[15];
    float* out = (float*)d_out;

    cudaFuncSetAttribute(main_kernel,
                         cudaFuncAttributeMaxDynamicSharedMemorySize, SMEM_BYTES);

    compact_kernel<<<BB * 128, 256>>>(ppos, lpos, pt, lt);
    main_kernel<<<GRIDX, 256, SMEM_BYTES>>>(pemb, lemb, W1, b1, W2, b2, W3, b3);
    finalize_kernel<<<BB, 1024>>>(Wr1, br1, Wr2, br2, out);
}